// round 2
// baseline (speedup 1.0000x reference)
#include <cuda_runtime.h>

// Problem constants (fixed shapes for this problem)
#define N   6144
#define FI  256
#define FO  64
#define NW  192            // mask words per row (N/32)
#define ALPHA 0.2f
#define TR  64             // rows per block in attention pass
#define JC  32             // j chunk
#define JH  3072           // j per split (N/2)

// Scratch (device globals: allocation-free rule)
__device__ __align__(16) float    g_Wh[N * FO];          // 1.5 MB
__device__ __align__(16) float    g_s1[N];
__device__ __align__(16) float    g_s2[N];
__device__ __align__(16) float    g_m1[N];
__device__ __align__(16) float    g_al[N];               // w0 / Z1
__device__ __align__(16) unsigned g_mask[(size_t)N * NW]; // 4.7 MB bit-packed adj
__device__ __align__(16) float    g_acc[2][(size_t)N * FO]; // 3.1 MB partial PV
__device__ __align__(16) float    g_Z2[2][N];

// ---- packed f32x2 helpers (sm_103a FFMA2 path) ----
__device__ __forceinline__ unsigned long long dup_f32(float x) {
    unsigned long long r;
    asm("mov.b64 %0, {%1, %1};" : "=l"(r) : "f"(x));
    return r;
}
__device__ __forceinline__ unsigned long long ffma2(unsigned long long a,
                                                    unsigned long long b,
                                                    unsigned long long c) {
    unsigned long long d;
    asm("fma.rn.f32x2 %0, %1, %2, %3;" : "=l"(d) : "l"(a), "l"(b), "l"(c));
    return d;
}
__device__ __forceinline__ float2 unpack_f32x2(unsigned long long v) {
    float2 f;
    asm("mov.b64 {%0, %1}, %2;" : "=f"(f.x), "=f"(f.y) : "l"(v));
    return f;
}

// ============================================================
// K1: Wh = h @ W   (32 rows per block)
// ============================================================
__global__ __launch_bounds__(256) void k_wh(const float* __restrict__ h,
                                            const float* __restrict__ W) {
    __shared__ float hs[32][FI];   // 32 KB
    int t = threadIdx.x;
    int row0 = blockIdx.x * 32;
    {
        const float4* src = (const float4*)(h + (size_t)row0 * FI);
        float4* dst = (float4*)&hs[0][0];
        for (int k = t; k < 32 * FI / 4; k += 256) dst[k] = src[k];
    }
    __syncthreads();
    int c = t & 63, r0 = t >> 6;
    float acc[8] = {0, 0, 0, 0, 0, 0, 0, 0};
#pragma unroll 4
    for (int kk = 0; kk < FI; kk += 4) {
        float w0 = __ldg(&W[(kk + 0) * FO + c]);
        float w1 = __ldg(&W[(kk + 1) * FO + c]);
        float w2 = __ldg(&W[(kk + 2) * FO + c]);
        float w3 = __ldg(&W[(kk + 3) * FO + c]);
#pragma unroll
        for (int q = 0; q < 8; q++) {
            float4 hv = *(const float4*)&hs[r0 + 4 * q][kk];
            acc[q] = fmaf(hv.x, w0, acc[q]);
            acc[q] = fmaf(hv.y, w1, acc[q]);
            acc[q] = fmaf(hv.z, w2, acc[q]);
            acc[q] = fmaf(hv.w, w3, acc[q]);
        }
    }
#pragma unroll
    for (int q = 0; q < 8; q++)
        g_Wh[(size_t)(row0 + r0 + 4 * q) * FO + c] = acc[q];
}

// ============================================================
// K2: s1[i] = Wh[i]·a[0:64], s2[i] = Wh[i]·a[64:128]
// ============================================================
__global__ __launch_bounds__(256) void k_s12(const float* __restrict__ a) {
    int i = blockIdx.x * 8 + (threadIdx.x >> 5);
    int l = threadIdx.x & 31;
    float wlo = g_Wh[(size_t)i * FO + l];
    float whi = g_Wh[(size_t)i * FO + 32 + l];
    float v1 = wlo * __ldg(&a[l]) + whi * __ldg(&a[32 + l]);
    float v2 = wlo * __ldg(&a[64 + l]) + whi * __ldg(&a[96 + l]);
#pragma unroll
    for (int o = 16; o; o >>= 1) {
        v1 += __shfl_xor_sync(0xffffffffu, v1, o);
        v2 += __shfl_xor_sync(0xffffffffu, v2, o);
    }
    if (l == 0) { g_s1[i] = v1; g_s2[i] = v2; }
}

// ============================================================
// K3: bitmask compression + per-row softmax-1 stats (m1, w0/Z1)
// 8 rows per block; adj read ONCE here.
// ============================================================
__global__ __launch_bounds__(256) void k_stats(const int* __restrict__ adj,
                                               const float* __restrict__ aw) {
    __shared__ float s2s[N];     // 24 KB
    __shared__ float red[256];
    int t = threadIdx.x;
    for (int k = t; k < N; k += 256) s2s[k] = g_s2[k];
    float aw0 = __ldg(&aw[0]), aw1 = __ldg(&aw[1]);
    float ea = __expf(aw0), eb = __expf(aw1);
    float w0 = ea / (ea + eb);
    __syncthreads();

    for (int r = 0; r < 8; r++) {
        int i = blockIdx.x * 8 + r;
        unsigned word = 0;
        float mx = -3e38f;
        if (t < NW) {
            const int4* ap = (const int4*)(adj + (size_t)i * N + t * 32);
#pragma unroll
            for (int q = 0; q < 8; q++) {
                int4 v = __ldg(&ap[q]);
                int base = q * 4;
                if (v.x) { word |= 1u << (base + 0); mx = fmaxf(mx, s2s[t * 32 + base + 0]); }
                if (v.y) { word |= 1u << (base + 1); mx = fmaxf(mx, s2s[t * 32 + base + 1]); }
                if (v.z) { word |= 1u << (base + 2); mx = fmaxf(mx, s2s[t * 32 + base + 2]); }
                if (v.w) { word |= 1u << (base + 3); mx = fmaxf(mx, s2s[t * 32 + base + 3]); }
            }
            g_mask[(size_t)i * NW + t] = word;
        }
        // block max reduce
        red[t] = mx;
        __syncthreads();
        for (int s = 128; s; s >>= 1) {
            if (t < s) red[t] = fmaxf(red[t], red[t + s]);
            __syncthreads();
        }
        float ms2 = red[0];
        __syncthreads();
        float s1i = g_s1[i];
        float x = s1i + ms2;
        float m1 = fmaxf(x, ALPHA * x);   // leaky_relu is monotone -> true row max
        float z = 0.f;
        if (t < NW) {
#pragma unroll 8
            for (int b = 0; b < 32; b++) {
                if ((word >> b) & 1u) {
                    float xx = s1i + s2s[t * 32 + b];
                    float v = fmaxf(xx, ALPHA * xx);
                    z += __expf(v - m1);
                }
            }
        }
        red[t] = z;
        __syncthreads();
        for (int s = 128; s; s >>= 1) {
            if (t < s) red[t] += red[t + s];
            __syncthreads();
        }
        if (t == 0) { g_m1[i] = m1; g_al[i] = w0 / red[0]; }
        __syncthreads();
    }
}

// ============================================================
// K4: fused pass: scores -> fixed-ref exp -> PV accumulate (FFMA2)
// grid (N/TR, 2): blockIdx.y = j-split. Partials -> g_acc / g_Z2.
// ============================================================
__global__ __launch_bounds__(256) void k_attn(const float* __restrict__ Mm,
                                              const float* __restrict__ aw) {
    __shared__ float s2s[JH];        // 12 KB (this split's half of s2)
    __shared__ float ps[TR][40];     // p tile, padded stride (10.2 KB)
    __shared__ float whs[JC][FO];    // Wh chunk (8 KB)

    int t = threadIdx.x;
    int row0 = blockIdx.x * TR;
    int split = blockIdx.y;
    int j0 = split * JH;

    for (int k = t; k < JH; k += 256) s2s[k] = g_s2[j0 + k];

    float aw0 = __ldg(&aw[0]), aw1 = __ldg(&aw[1]);
    float ea = __expf(aw0), eb = __expf(aw1);
    float w1 = eb / (ea + eb);

    // score-phase mapping: thread owns row rs, 8 j positions per chunk
    int rs = t >> 2;                 // 0..63
    int jq = t & 3;
    float s1r = g_s1[row0 + rs];
    float m1r = g_m1[row0 + rs];
    float alr = g_al[row0 + rs];

    // PV mapping: col pair cp, row group rg (8 rows: rg+8q)
    int cp = t & 31, rg = t >> 5;
    unsigned long long acc[8];
#pragma unroll
    for (int q = 0; q < 8; q++) acc[q] = 0ull;
    float zacc = 0.f;

    const float* Mrow = Mm + (size_t)(row0 + rs) * N + j0;
    const unsigned* mrow = g_mask + (size_t)(row0 + rs) * NW + (j0 >> 5);

    __syncthreads();

    for (int ch = 0; ch < JH / JC; ch++) {
        int jb = ch * JC;
        // stage Wh chunk
        {
            const float4* src = (const float4*)(g_Wh + (size_t)(j0 + jb) * FO);
            float4* dst = (float4*)&whs[0][0];
#pragma unroll
            for (int k = 0; k < 2; k++) dst[t + 256 * k] = src[t + 256 * k];
        }
        // compute p for this chunk (8 elems/thread)
        unsigned word = mrow[ch];
#pragma unroll
        for (int h2 = 0; h2 < 2; h2++) {
            int jj = jq * 4 + h2 * 16;
            float4 m4 = *(const float4*)(Mrow + jb + jj);
            float p0, p1, p2, p3;
            {
                float x, v, e1, tt;
                x = s1r + s2s[jb + jj + 0]; v = fmaxf(x, ALPHA * x);
                e1 = alr * __expf(v - m1r); tt = fmaf(w1, m4.x, e1);
                p0 = ((word >> (jj + 0)) & 1u) ? __expf(tt) : 0.f;
                x = s1r + s2s[jb + jj + 1]; v = fmaxf(x, ALPHA * x);
                e1 = alr * __expf(v - m1r); tt = fmaf(w1, m4.y, e1);
                p1 = ((word >> (jj + 1)) & 1u) ? __expf(tt) : 0.f;
                x = s1r + s2s[jb + jj + 2]; v = fmaxf(x, ALPHA * x);
                e1 = alr * __expf(v - m1r); tt = fmaf(w1, m4.z, e1);
                p2 = ((word >> (jj + 2)) & 1u) ? __expf(tt) : 0.f;
                x = s1r + s2s[jb + jj + 3]; v = fmaxf(x, ALPHA * x);
                e1 = alr * __expf(v - m1r); tt = fmaf(w1, m4.w, e1);
                p3 = ((word >> (jj + 3)) & 1u) ? __expf(tt) : 0.f;
            }
            zacc += (p0 + p1) + (p2 + p3);
            *(float4*)&ps[rs][jj] = make_float4(p0, p1, p2, p3);
        }
        __syncthreads();
        // PV accumulate: FFMA2, 8 rows x 1 col-pair per thread
#pragma unroll
        for (int j4 = 0; j4 < 8; j4++) {
            unsigned long long wh2[4];
#pragma unroll
            for (int m = 0; m < 4; m++)
                wh2[m] = *(const unsigned long long*)&whs[j4 * 4 + m][2 * cp];
#pragma unroll
            for (int q = 0; q < 8; q++) {
                float4 p4 = *(const float4*)&ps[rg + 8 * q][j4 * 4];
                acc[q] = ffma2(dup_f32(p4.x), wh2[0], acc[q]);
                acc[q] = ffma2(dup_f32(p4.y), wh2[1], acc[q]);
                acc[q] = ffma2(dup_f32(p4.z), wh2[2], acc[q]);
                acc[q] = ffma2(dup_f32(p4.w), wh2[3], acc[q]);
            }
        }
        __syncthreads();
    }

    // Z2 partial: reduce the 4 threads (jq) sharing row rs
    zacc += __shfl_xor_sync(0xffffffffu, zacc, 1);
    zacc += __shfl_xor_sync(0xffffffffu, zacc, 2);
    if (jq == 0) g_Z2[split][row0 + rs] = zacc;

    // store PV partials
#pragma unroll
    for (int q = 0; q < 8; q++) {
        float2 f = unpack_f32x2(acc[q]);
        *(float2*)&g_acc[split][(size_t)(row0 + rg + 8 * q) * FO + 2 * cp] = f;
    }
}

// ============================================================
// K5: combine splits, normalize, ELU
// ============================================================
__global__ __launch_bounds__(256) void k_out(float* __restrict__ out) {
    int idx = blockIdx.x * 256 + threadIdx.x;
    int i = idx >> 6;
    float z = g_Z2[0][i] + g_Z2[1][i];
    float v = (g_acc[0][idx] + g_acc[1][idx]) / z;
    out[idx] = v > 0.f ? v : (__expf(v) - 1.f);
}

// ============================================================
extern "C" void kernel_launch(void* const* d_in, const int* in_sizes, int n_in,
                              void* d_out, int out_size) {
    const float* h   = (const float*)d_in[0];
    const int*   adj = (const int*)d_in[1];
    const float* Mm  = (const float*)d_in[2];
    const float* W   = (const float*)d_in[3];
    const float* a   = (const float*)d_in[4];
    const float* aw  = (const float*)d_in[5];
    float* out = (float*)d_out;

    k_wh   <<<N / 32, 256>>>(h, W);
    k_s12  <<<N / 8, 256>>>(a);
    k_stats<<<N / 8, 256>>>(adj, aw);
    dim3 g4(N / TR, 2);
    k_attn <<<g4, 256>>>(Mm, aw);
    k_out  <<<N * FO / 256, 256>>>(out);
}

// round 3
// speedup vs baseline: 1.8860x; 1.8860x over previous
#include <cuda_runtime.h>

// Problem constants
#define N   6144
#define FI  256
#define FO  64
#define NW  192            // mask words per row (N/32)
#define ALPHA 0.2f
#define TR  32             // rows per block in attention pass
#define JC  32             // j chunk
#define SPLITS 4
#define JH  (N / SPLITS)   // 1536 j per split

// Scratch (device globals: allocation-free rule)
__device__ __align__(16) float    g_Wh[N * FO];              // 1.5 MB
__device__ __align__(16) float    g_s1[N];
__device__ __align__(16) float    g_s2[N];
__device__ __align__(16) float    g_m1[N];
__device__ __align__(16) float    g_al[N];                   // w0 / Z1
__device__ __align__(16) unsigned g_mask[(size_t)N * NW];    // 4.7 MB bit-packed adj
__device__ __align__(16) float    g_acc[SPLITS][(size_t)N * FO]; // 6.3 MB partial PV
__device__ __align__(16) float    g_Z2[SPLITS][N];

// ---- packed f32x2 helpers (sm_103a FFMA2 path) ----
__device__ __forceinline__ unsigned long long dup_f32(float x) {
    unsigned long long r;
    asm("mov.b64 %0, {%1, %1};" : "=l"(r) : "f"(x));
    return r;
}
__device__ __forceinline__ unsigned long long ffma2(unsigned long long a,
                                                    unsigned long long b,
                                                    unsigned long long c) {
    unsigned long long d;
    asm("fma.rn.f32x2 %0, %1, %2, %3;" : "=l"(d) : "l"(a), "l"(b), "l"(c));
    return d;
}
__device__ __forceinline__ float2 unpack_f32x2(unsigned long long v) {
    float2 f;
    asm("mov.b64 {%0, %1}, %2;" : "=f"(f.x), "=f"(f.y) : "l"(v));
    return f;
}

// ============================================================
// K1: Wh = h @ W   (32 rows per block)
// ============================================================
__global__ __launch_bounds__(256) void k_wh(const float* __restrict__ h,
                                            const float* __restrict__ W) {
    __shared__ float hs[32][FI];   // 32 KB
    int t = threadIdx.x;
    int row0 = blockIdx.x * 32;
    {
        const float4* src = (const float4*)(h + (size_t)row0 * FI);
        float4* dst = (float4*)&hs[0][0];
        for (int k = t; k < 32 * FI / 4; k += 256) dst[k] = src[k];
    }
    __syncthreads();
    int c = t & 63, r0 = t >> 6;
    float acc[8] = {0, 0, 0, 0, 0, 0, 0, 0};
#pragma unroll 4
    for (int kk = 0; kk < FI; kk += 4) {
        float w0 = __ldg(&W[(kk + 0) * FO + c]);
        float w1 = __ldg(&W[(kk + 1) * FO + c]);
        float w2 = __ldg(&W[(kk + 2) * FO + c]);
        float w3 = __ldg(&W[(kk + 3) * FO + c]);
#pragma unroll
        for (int q = 0; q < 8; q++) {
            float4 hv = *(const float4*)&hs[r0 + 4 * q][kk];
            acc[q] = fmaf(hv.x, w0, acc[q]);
            acc[q] = fmaf(hv.y, w1, acc[q]);
            acc[q] = fmaf(hv.z, w2, acc[q]);
            acc[q] = fmaf(hv.w, w3, acc[q]);
        }
    }
#pragma unroll
    for (int q = 0; q < 8; q++)
        g_Wh[(size_t)(row0 + r0 + 4 * q) * FO + c] = acc[q];
}

// ============================================================
// K2: s1[i] = Wh[i]·a[0:64], s2[i] = Wh[i]·a[64:128]
// ============================================================
__global__ __launch_bounds__(256) void k_s12(const float* __restrict__ a) {
    int i = blockIdx.x * 8 + (threadIdx.x >> 5);
    int l = threadIdx.x & 31;
    float wlo = g_Wh[(size_t)i * FO + l];
    float whi = g_Wh[(size_t)i * FO + 32 + l];
    float v1 = wlo * __ldg(&a[l]) + whi * __ldg(&a[32 + l]);
    float v2 = wlo * __ldg(&a[64 + l]) + whi * __ldg(&a[96 + l]);
#pragma unroll
    for (int o = 16; o; o >>= 1) {
        v1 += __shfl_xor_sync(0xffffffffu, v1, o);
        v2 += __shfl_xor_sync(0xffffffffu, v2, o);
    }
    if (l == 0) { g_s1[i] = v1; g_s2[i] = v2; }
}

// ============================================================
// K3: bitmask build + per-row softmax-1 stats. ONE WARP PER ROW.
// Fully coalesced LDG.32 + ballot; shfl-only reductions; no block barriers.
// ============================================================
__global__ __launch_bounds__(256) void k_stats(const int* __restrict__ adj,
                                               const float* __restrict__ aw) {
    int warp = threadIdx.x >> 5, lane = threadIdx.x & 31;
    int i = blockIdx.x * 8 + warp;

    float aw0 = __ldg(&aw[0]), aw1 = __ldg(&aw[1]);
    float ea = __expf(aw0), eb = __expf(aw1);
    float w0 = ea / (ea + eb);

    const int* row = adj + (size_t)i * N;
    float s1i = g_s1[i];
    float mx = -3e38f;
    unsigned words[6];           // lane-distributed: lane l holds words wi with wi%32==l

#pragma unroll
    for (int g = 0; g < 6; g++) {
        unsigned mine = 0;
#pragma unroll
        for (int k = 0; k < 32; k++) {
            int wi = g * 32 + k;
            int v = __ldg(&row[wi * 32 + lane]);           // coalesced 128B
            unsigned wm = __ballot_sync(0xffffffffu, v != 0);
            if (k == lane) mine = wm;
            if (v) mx = fmaxf(mx, __ldg(&g_s2[wi * 32 + lane]));
        }
        words[g] = mine;
        g_mask[(size_t)i * NW + g * 32 + lane] = mine;     // coalesced store
    }
    // warp max reduce
#pragma unroll
    for (int o = 16; o; o >>= 1) mx = fmaxf(mx, __shfl_xor_sync(0xffffffffu, mx, o));
    float x = s1i + mx;
    float m1 = fmaxf(x, ALPHA * x);                        // lrelu monotone -> true row max
    // pass 2: Z1
    float z = 0.f;
#pragma unroll
    for (int g = 0; g < 6; g++) {
#pragma unroll
        for (int k = 0; k < 32; k++) {
            unsigned wm = __shfl_sync(0xffffffffu, words[g], k);
            if ((wm >> lane) & 1u) {
                float xx = s1i + __ldg(&g_s2[(g * 32 + k) * 32 + lane]);
                float v = fmaxf(xx, ALPHA * xx);
                z += __expf(v - m1);
            }
        }
    }
#pragma unroll
    for (int o = 16; o; o >>= 1) z += __shfl_xor_sync(0xffffffffu, z, o);
    if (lane == 0) { g_m1[i] = m1; g_al[i] = w0 / z; }
}

// ============================================================
// K4: fused scores -> fixed-ref exp -> PV accumulate (FFMA2)
// grid (N/TR, SPLITS). TR=32 rows, 4 j-splits -> 768 CTAs.
// ============================================================
__global__ __launch_bounds__(256) void k_attn(const float* __restrict__ Mm,
                                              const float* __restrict__ aw) {
    __shared__ float s2s[JH];        // 6 KB
    __shared__ float ps[TR][36];     // p tile, padded (4.5 KB)
    __shared__ float whs[JC][FO];    // Wh chunk (8 KB)

    int t = threadIdx.x;
    int row0 = blockIdx.x * TR;
    int split = blockIdx.y;
    int j0 = split * JH;

    for (int k = t; k < JH; k += 256) s2s[k] = g_s2[j0 + k];

    float aw0 = __ldg(&aw[0]), aw1 = __ldg(&aw[1]);
    float ea = __expf(aw0), eb = __expf(aw1);
    float w1 = eb / (ea + eb);

    // score mapping: thread owns row rs, 4 j positions per chunk
    int rs = t >> 3;                 // 0..31
    int jq = t & 7;                  // 0..7
    float s1r = g_s1[row0 + rs];
    float m1r = g_m1[row0 + rs];
    float alr = g_al[row0 + rs];

    // PV mapping: col pair cp, 4 rows rg+8q
    int cp = t & 31, rg = t >> 5;
    unsigned long long acc[4] = {0ull, 0ull, 0ull, 0ull};
    float zacc = 0.f;

    const float* Mrow = Mm + (size_t)(row0 + rs) * N + j0;
    const unsigned* mrow = g_mask + (size_t)(row0 + rs) * NW + (j0 >> 5);

    __syncthreads();

    for (int ch = 0; ch < JH / JC; ch++) {
        int jb = ch * JC;
        // stage Wh chunk (512 float4)
        {
            const float4* src = (const float4*)(g_Wh + (size_t)(j0 + jb) * FO);
            float4* dst = (float4*)&whs[0][0];
            dst[t] = src[t];
            dst[t + 256] = src[t + 256];
        }
        // compute p: 4 elems/thread
        unsigned word = mrow[ch];
        int jj = jq * 4;
        {
            float4 m4 = *(const float4*)(Mrow + jb + jj);
            float p0, p1, p2, p3;
            float x, v, e1, tt;
            x = s1r + s2s[jb + jj + 0]; v = fmaxf(x, ALPHA * x);
            e1 = alr * __expf(v - m1r); tt = fmaf(w1, m4.x, e1);
            p0 = ((word >> (jj + 0)) & 1u) ? __expf(tt) : 0.f;
            x = s1r + s2s[jb + jj + 1]; v = fmaxf(x, ALPHA * x);
            e1 = alr * __expf(v - m1r); tt = fmaf(w1, m4.y, e1);
            p1 = ((word >> (jj + 1)) & 1u) ? __expf(tt) : 0.f;
            x = s1r + s2s[jb + jj + 2]; v = fmaxf(x, ALPHA * x);
            e1 = alr * __expf(v - m1r); tt = fmaf(w1, m4.z, e1);
            p2 = ((word >> (jj + 2)) & 1u) ? __expf(tt) : 0.f;
            x = s1r + s2s[jb + jj + 3]; v = fmaxf(x, ALPHA * x);
            e1 = alr * __expf(v - m1r); tt = fmaf(w1, m4.w, e1);
            p3 = ((word >> (jj + 3)) & 1u) ? __expf(tt) : 0.f;
            zacc += (p0 + p1) + (p2 + p3);
            *(float4*)&ps[rs][jj] = make_float4(p0, p1, p2, p3);
        }
        __syncthreads();
        // PV accumulate: FFMA2, 4 rows x 1 col-pair per thread
#pragma unroll
        for (int j4 = 0; j4 < 8; j4++) {
            unsigned long long wh2[4];
#pragma unroll
            for (int m = 0; m < 4; m++)
                wh2[m] = *(const unsigned long long*)&whs[j4 * 4 + m][2 * cp];
#pragma unroll
            for (int q = 0; q < 4; q++) {
                float4 p4 = *(const float4*)&ps[rg + 8 * q][j4 * 4];
                acc[q] = ffma2(dup_f32(p4.x), wh2[0], acc[q]);
                acc[q] = ffma2(dup_f32(p4.y), wh2[1], acc[q]);
                acc[q] = ffma2(dup_f32(p4.z), wh2[2], acc[q]);
                acc[q] = ffma2(dup_f32(p4.w), wh2[3], acc[q]);
            }
        }
        __syncthreads();
    }

    // Z2 partial: reduce 8 threads (jq) sharing row rs (consecutive lanes)
    zacc += __shfl_xor_sync(0xffffffffu, zacc, 1);
    zacc += __shfl_xor_sync(0xffffffffu, zacc, 2);
    zacc += __shfl_xor_sync(0xffffffffu, zacc, 4);
    if (jq == 0) g_Z2[split][row0 + rs] = zacc;

    // store PV partials
#pragma unroll
    for (int q = 0; q < 4; q++) {
        float2 f = unpack_f32x2(acc[q]);
        *(float2*)&g_acc[split][(size_t)(row0 + rg + 8 * q) * FO + 2 * cp] = f;
    }
}

// ============================================================
// K5: combine splits, normalize, ELU
// ============================================================
__global__ __launch_bounds__(256) void k_out(float* __restrict__ out) {
    int idx = blockIdx.x * 256 + threadIdx.x;
    int i = idx >> 6;
    float z = g_Z2[0][i] + g_Z2[1][i] + g_Z2[2][i] + g_Z2[3][i];
    float v = (g_acc[0][idx] + g_acc[1][idx] + g_acc[2][idx] + g_acc[3][idx]) / z;
    out[idx] = v > 0.f ? v : (__expf(v) - 1.f);
}

// ============================================================
extern "C" void kernel_launch(void* const* d_in, const int* in_sizes, int n_in,
                              void* d_out, int out_size) {
    const float* h   = (const float*)d_in[0];
    const int*   adj = (const int*)d_in[1];
    const float* Mm  = (const float*)d_in[2];
    const float* W   = (const float*)d_in[3];
    const float* a   = (const float*)d_in[4];
    const float* aw  = (const float*)d_in[5];
    float* out = (float*)d_out;

    k_wh   <<<N / 32, 256>>>(h, W);
    k_s12  <<<N / 8, 256>>>(a);
    k_stats<<<N / 8, 256>>>(adj, aw);
    dim3 g4(N / TR, SPLITS);
    k_attn <<<g4, 256>>>(Mm, aw);
    k_out  <<<N * FO / 256, 256>>>(out);
}

// round 5
// speedup vs baseline: 2.9976x; 1.5894x over previous
#include <cuda_runtime.h>

// Problem constants
#define N   6144
#define FI  256
#define FO  64
#define NB  768            // mask bytes per row (N/8)
#define ALPHA 0.2f
#define TR  64             // rows per block in attention pass
#define JC  32             // j chunk
#define SPLITS 4
#define JH  (N / SPLITS)   // 1536 j per split

// Scratch (device globals: allocation-free rule)
__device__ __align__(16) float         g_Wh[N * FO];              // 1.5 MB
__device__ __align__(16) float         g_s1[N];
__device__ __align__(16) float         g_s2[N];
__device__ __align__(16) float         g_al[N];                   // w0 / Z1
__device__ __align__(16) unsigned char g_mask8[(size_t)N * NB];   // 4.7 MB bit-packed adj
__device__ __align__(16) float         g_acc[SPLITS][(size_t)N * FO]; // 6.3 MB partial PV
__device__ __align__(16) float         g_Z2[SPLITS][N];

// ---- packed f32x2 helpers (sm_103a FFMA2 path) ----
__device__ __forceinline__ unsigned long long dup_f32(float x) {
    unsigned long long r;
    asm("mov.b64 %0, {%1, %1};" : "=l"(r) : "f"(x));
    return r;
}
__device__ __forceinline__ unsigned long long ffma2(unsigned long long a,
                                                    unsigned long long b,
                                                    unsigned long long c) {
    unsigned long long d;
    asm("fma.rn.f32x2 %0, %1, %2, %3;" : "=l"(d) : "l"(a), "l"(b), "l"(c));
    return d;
}
__device__ __forceinline__ float2 unpack_f32x2(unsigned long long v) {
    float2 f;
    asm("mov.b64 {%0, %1}, %2;" : "=f"(f.x), "=f"(f.y) : "l"(v));
    return f;
}

// ============================================================
// K1: Wh = h @ W   (32 rows per block)
// ============================================================
__global__ __launch_bounds__(256) void k_wh(const float* __restrict__ h,
                                            const float* __restrict__ W) {
    __shared__ float hs[32][FI];   // 32 KB
    int t = threadIdx.x;
    int row0 = blockIdx.x * 32;
    {
        const float4* src = (const float4*)(h + (size_t)row0 * FI);
        float4* dst = (float4*)&hs[0][0];
        for (int k = t; k < 32 * FI / 4; k += 256) dst[k] = src[k];
    }
    __syncthreads();
    int c = t & 63, r0 = t >> 6;
    float acc[8] = {0, 0, 0, 0, 0, 0, 0, 0};
#pragma unroll 4
    for (int kk = 0; kk < FI; kk += 4) {
        float w0 = __ldg(&W[(kk + 0) * FO + c]);
        float w1 = __ldg(&W[(kk + 1) * FO + c]);
        float w2 = __ldg(&W[(kk + 2) * FO + c]);
        float w3 = __ldg(&W[(kk + 3) * FO + c]);
#pragma unroll
        for (int q = 0; q < 8; q++) {
            float4 hv = *(const float4*)&hs[r0 + 4 * q][kk];
            acc[q] = fmaf(hv.x, w0, acc[q]);
            acc[q] = fmaf(hv.y, w1, acc[q]);
            acc[q] = fmaf(hv.z, w2, acc[q]);
            acc[q] = fmaf(hv.w, w3, acc[q]);
        }
    }
#pragma unroll
    for (int q = 0; q < 8; q++)
        g_Wh[(size_t)(row0 + r0 + 4 * q) * FO + c] = acc[q];
}

// ============================================================
// K2: s1[i] = Wh[i]·a[0:64], s2[i] = Wh[i]·a[64:128]
// ============================================================
__global__ __launch_bounds__(256) void k_s12(const float* __restrict__ a) {
    int i = blockIdx.x * 8 + (threadIdx.x >> 5);
    int l = threadIdx.x & 31;
    float wlo = g_Wh[(size_t)i * FO + l];
    float whi = g_Wh[(size_t)i * FO + 32 + l];
    float v1 = wlo * __ldg(&a[l]) + whi * __ldg(&a[32 + l]);
    float v2 = wlo * __ldg(&a[64 + l]) + whi * __ldg(&a[96 + l]);
#pragma unroll
    for (int o = 16; o; o >>= 1) {
        v1 += __shfl_xor_sync(0xffffffffu, v1, o);
        v2 += __shfl_xor_sync(0xffffffffu, v2, o);
    }
    if (l == 0) { g_s1[i] = v1; g_s2[i] = v2; }
}

// ============================================================
// K3: SINGLE-PASS mask build + Z1.  One warp per row.
// No max subtraction needed: |s1+s2| bounded -> exp() fp32-safe.
// Lane l owns j = m*256 + 8l .. +7  (two int4 loads, coalesced 1KB/warp).
// Mask byte bit k <-> j = 8*(byte_index)+k  (little-endian word reads later).
// ============================================================
__global__ __launch_bounds__(256) void k_stats(const int* __restrict__ adj,
                                               const float* __restrict__ aw) {
    int warp = threadIdx.x >> 5, lane = threadIdx.x & 31;
    int i = blockIdx.x * 8 + warp;

    float aw0 = __ldg(&aw[0]), aw1 = __ldg(&aw[1]);
    float ea = __expf(aw0), eb = __expf(aw1);
    float w0 = ea / (ea + eb);

    const int* row = adj + (size_t)i * N;
    float s1i = g_s1[i];
    float z = 0.f;

#pragma unroll 4
    for (int m = 0; m < N / 256; m++) {
        int jb = m * 256 + lane * 8;
        int4 v0 = __ldg((const int4*)(row + jb));
        int4 v1 = __ldg((const int4*)(row + jb + 4));
        float4 sa = *(const float4*)(g_s2 + jb);
        float4 sb = *(const float4*)(g_s2 + jb + 4);
        unsigned b = 0;
        float x;
        if (v0.x) { b |= 1u;   x = s1i + sa.x; z += __expf(fmaxf(x, ALPHA * x)); }
        if (v0.y) { b |= 2u;   x = s1i + sa.y; z += __expf(fmaxf(x, ALPHA * x)); }
        if (v0.z) { b |= 4u;   x = s1i + sa.z; z += __expf(fmaxf(x, ALPHA * x)); }
        if (v0.w) { b |= 8u;   x = s1i + sa.w; z += __expf(fmaxf(x, ALPHA * x)); }
        if (v1.x) { b |= 16u;  x = s1i + sb.x; z += __expf(fmaxf(x, ALPHA * x)); }
        if (v1.y) { b |= 32u;  x = s1i + sb.y; z += __expf(fmaxf(x, ALPHA * x)); }
        if (v1.z) { b |= 64u;  x = s1i + sb.z; z += __expf(fmaxf(x, ALPHA * x)); }
        if (v1.w) { b |= 128u; x = s1i + sb.w; z += __expf(fmaxf(x, ALPHA * x)); }
        g_mask8[(size_t)i * NB + m * 32 + lane] = (unsigned char)b;
    }
#pragma unroll
    for (int o = 16; o; o >>= 1) z += __shfl_xor_sync(0xffffffffu, z, o);
    if (lane == 0) g_al[i] = w0 / z;
}

// ============================================================
// K4: fused scores -> exp -> PV accumulate (FFMA2)
// grid (N/TR, SPLITS) = (96, 4) = 384 CTAs, 3 resident/SM (one wave).
// TR=64: whs crossbar bytes amortized over 8 rows/warp.
// ============================================================
__global__ __launch_bounds__(256, 3) void k_attn(const float* __restrict__ Mm,
                                                 const float* __restrict__ aw) {
    __shared__ float s2s[JH];        // 6 KB
    __shared__ float ps[TR][48];     // 12.3 KB, stride 48: conflict-free f4 stores
    __shared__ float whs[JC][FO];    // 8 KB

    int t = threadIdx.x;
    int row0 = blockIdx.x * TR;
    int split = blockIdx.y;
    int j0 = split * JH;

    for (int k = t; k < JH; k += 256) s2s[k] = g_s2[j0 + k];

    float aw0 = __ldg(&aw[0]), aw1 = __ldg(&aw[1]);
    float ea = __expf(aw0), eb = __expf(aw1);
    float w1 = eb / (ea + eb);

    // score mapping: thread owns row rs, 8 j per chunk (2 x float4)
    int rs = t >> 2;                 // 0..63
    int jq = t & 3;                  // 0..3
    float s1r = g_s1[row0 + rs];
    float alr = g_al[row0 + rs];

    // PV mapping: col-pair cp, 8 rows rg+8q
    int cp = t & 31, rg = t >> 5;
    unsigned long long acc[8];
#pragma unroll
    for (int q = 0; q < 8; q++) acc[q] = 0ull;
    float zacc = 0.f;

    const float* Mrow = Mm + (size_t)(row0 + rs) * N + j0;
    const unsigned* mrow =
        (const unsigned*)(g_mask8 + (size_t)(row0 + rs) * NB + (j0 >> 3));

    __syncthreads();

    for (int ch = 0; ch < JH / JC; ch++) {
        int jb = ch * JC;
        // stage Wh chunk (512 float4)
        {
            const float4* src = (const float4*)(g_Wh + (size_t)(j0 + jb) * FO);
            float4* dst = (float4*)&whs[0][0];
            dst[t] = src[t];
            dst[t + 256] = src[t + 256];
        }
        // compute p: 8 elems/thread
        unsigned word = mrow[ch];
#pragma unroll
        for (int h2 = 0; h2 < 2; h2++) {
            int jj = jq * 4 + h2 * 16;
            float4 m4 = *(const float4*)(Mrow + jb + jj);
            float p0, p1, p2, p3;
            float x, v, e1, tt;
            x = s1r + s2s[jb + jj + 0]; v = fmaxf(x, ALPHA * x);
            e1 = alr * __expf(v); tt = fmaf(w1, m4.x, e1);
            p0 = ((word >> (jj + 0)) & 1u) ? __expf(tt) : 0.f;
            x = s1r + s2s[jb + jj + 1]; v = fmaxf(x, ALPHA * x);
            e1 = alr * __expf(v); tt = fmaf(w1, m4.y, e1);
            p1 = ((word >> (jj + 1)) & 1u) ? __expf(tt) : 0.f;
            x = s1r + s2s[jb + jj + 2]; v = fmaxf(x, ALPHA * x);
            e1 = alr * __expf(v); tt = fmaf(w1, m4.z, e1);
            p2 = ((word >> (jj + 2)) & 1u) ? __expf(tt) : 0.f;
            x = s1r + s2s[jb + jj + 3]; v = fmaxf(x, ALPHA * x);
            e1 = alr * __expf(v); tt = fmaf(w1, m4.w, e1);
            p3 = ((word >> (jj + 3)) & 1u) ? __expf(tt) : 0.f;
            zacc += (p0 + p1) + (p2 + p3);
            *(float4*)&ps[rs][jj] = make_float4(p0, p1, p2, p3);
        }
        __syncthreads();
        // PV accumulate: FFMA2, 8 rows x 1 col-pair per thread
#pragma unroll
        for (int j4 = 0; j4 < 8; j4++) {
            unsigned long long wh2[4];
#pragma unroll
            for (int m = 0; m < 4; m++)
                wh2[m] = *(const unsigned long long*)&whs[j4 * 4 + m][2 * cp];
#pragma unroll
            for (int q = 0; q < 8; q++) {
                float4 p4 = *(const float4*)&ps[rg + 8 * q][j4 * 4];
                acc[q] = ffma2(dup_f32(p4.x), wh2[0], acc[q]);
                acc[q] = ffma2(dup_f32(p4.y), wh2[1], acc[q]);
                acc[q] = ffma2(dup_f32(p4.z), wh2[2], acc[q]);
                acc[q] = ffma2(dup_f32(p4.w), wh2[3], acc[q]);
            }
        }
        __syncthreads();
    }

    // Z2 partial: reduce 4 threads (jq) sharing row rs (consecutive lanes)
    zacc += __shfl_xor_sync(0xffffffffu, zacc, 1);
    zacc += __shfl_xor_sync(0xffffffffu, zacc, 2);
    if (jq == 0) g_Z2[split][row0 + rs] = zacc;

    // store PV partials
#pragma unroll
    for (int q = 0; q < 8; q++) {
        float2 f = unpack_f32x2(acc[q]);
        *(float2*)&g_acc[split][(size_t)(row0 + rg + 8 * q) * FO + 2 * cp] = f;
    }
}

// ============================================================
// K5: combine splits, normalize, ELU
// ============================================================
__global__ __launch_bounds__(256) void k_out(float* __restrict__ out) {
    int idx = blockIdx.x * 256 + threadIdx.x;
    int i = idx >> 6;
    float z = g_Z2[0][i] + g_Z2[1][i] + g_Z2[2][i] + g_Z2[3][i];
    float v = (g_acc[0][idx] + g_acc[1][idx] + g_acc[2][idx] + g_acc[3][idx]) / z;
    out[idx] = v > 0.f ? v : (__expf(v) - 1.f);
}

// ============================================================
extern "C" void kernel_launch(void* const* d_in, const int* in_sizes, int n_in,
                              void* d_out, int out_size) {
    const float* h   = (const float*)d_in[0];
    const int*   adj = (const int*)d_in[1];
    const float* Mm  = (const float*)d_in[2];
    const float* W   = (const float*)d_in[3];
    const float* a   = (const float*)d_in[4];
    const float* aw  = (const float*)d_in[5];
    float* out = (float*)d_out;

    k_wh   <<<N / 32, 256>>>(h, W);
    k_s12  <<<N / 8, 256>>>(a);
    k_stats<<<N / 8, 256>>>(adj, aw);
    dim3 g4(N / TR, SPLITS);
    k_attn <<<g4, 256>>>(Mm, aw);
    k_out  <<<N * FO / 256, 256>>>(out);
}

// round 7
// speedup vs baseline: 4.4133x; 1.4723x over previous
#include <cuda_runtime.h>
#include <cuda_bf16.h>
#include <cstdint>

// Problem constants
#define N      6144
#define FI     256
#define FO     64
#define NB     768           // mask bytes per row (N/8)
#define ALPHA  0.2f
#define ROWS_T 128           // rows per CTA in attention pass (M tile)
#define KCH    64            // j per chunk (K tile)
#define SPLITS 6
#define JSP    (N / SPLITS)  // 1024
#define NCHUNK (JSP / KCH)   // 16

// Scratch (device globals: allocation-free rule)
__device__ __align__(16) float         g_Wh[N * FO];
__device__ __align__(16) float         g_s1[N];
__device__ __align__(16) float         g_s2[N];
__device__ __align__(16) float         g_al[N];                 // w0 / Z1
__device__ __align__(16) unsigned char g_mask8[(size_t)N * NB];
__device__ __align__(16) unsigned      g_WhT_hi[FO * (N / 2)];  // bf16x2 pairs, [c][jpair]
__device__ __align__(16) unsigned      g_WhT_lo[FO * (N / 2)];
__device__ __align__(16) float         g_acc[SPLITS][(size_t)N * FO];
__device__ __align__(16) float         g_Z2[SPLITS][N];

// ======================= helpers =======================
__device__ __forceinline__ uint32_t smem_u32(const void* p) {
    uint32_t a;
    asm("{ .reg .u64 t; cvta.to.shared.u64 t, %1; cvt.u32.u64 %0, t; }" : "=r"(a) : "l"(p));
    return a;
}
__device__ __forceinline__ uint32_t cvt_bf16x2(float lo, float hi) {
    uint32_t r;
    asm("cvt.rn.bf16x2.f32 %0, %1, %2;" : "=r"(r) : "f"(hi), "f"(lo));  // d.lo = 2nd operand
    return r;
}
__device__ __forceinline__ void ldsm_x4(uint32_t* r, uint32_t addr) {
    asm volatile("ldmatrix.sync.aligned.m8n8.x4.shared.b16 {%0,%1,%2,%3}, [%4];"
                 : "=r"(r[0]), "=r"(r[1]), "=r"(r[2]), "=r"(r[3]) : "r"(addr));
}
__device__ __forceinline__ void mma_bf16(float* c, const uint32_t* a, uint32_t b0, uint32_t b1) {
    asm volatile("mma.sync.aligned.m16n8k16.row.col.f32.bf16.bf16.f32 "
                 "{%0,%1,%2,%3}, {%4,%5,%6,%7}, {%8,%9}, {%0,%1,%2,%3};"
                 : "+f"(c[0]), "+f"(c[1]), "+f"(c[2]), "+f"(c[3])
                 : "r"(a[0]), "r"(a[1]), "r"(a[2]), "r"(a[3]), "r"(b0), "r"(b1));
}
#define SWZ(x) ((x) ^ (((x) >> 3) & 0x70))

// dynamic SMEM layout for k_attn
#define SM_S2S   0        // 1024 f32 = 4KB
#define SM_A_HI  4096     // 128 x 128B = 16KB  (P hi, row-major K, SW128)
#define SM_A_LO  20480    // 16KB
#define SM_B_HI  36864    // 64 x 128B = 8KB    (WhT hi, [n][k], SW128)
#define SM_B_LO  45056    // 8KB
#define SM_TOTAL 53248

// ============================================================
// K1: Wh = h @ W
// ============================================================
__global__ __launch_bounds__(256) void k_wh(const float* __restrict__ h,
                                            const float* __restrict__ W) {
    __shared__ float hs[32][FI];
    int t = threadIdx.x;
    int row0 = blockIdx.x * 32;
    {
        const float4* src = (const float4*)(h + (size_t)row0 * FI);
        float4* dst = (float4*)&hs[0][0];
        for (int k = t; k < 32 * FI / 4; k += 256) dst[k] = src[k];
    }
    __syncthreads();
    int c = t & 63, r0 = t >> 6;
    float acc[8] = {0, 0, 0, 0, 0, 0, 0, 0};
#pragma unroll 4
    for (int kk = 0; kk < FI; kk += 4) {
        float w0 = __ldg(&W[(kk + 0) * FO + c]);
        float w1 = __ldg(&W[(kk + 1) * FO + c]);
        float w2 = __ldg(&W[(kk + 2) * FO + c]);
        float w3 = __ldg(&W[(kk + 3) * FO + c]);
#pragma unroll
        for (int q = 0; q < 8; q++) {
            float4 hv = *(const float4*)&hs[r0 + 4 * q][kk];
            acc[q] = fmaf(hv.x, w0, acc[q]);
            acc[q] = fmaf(hv.y, w1, acc[q]);
            acc[q] = fmaf(hv.z, w2, acc[q]);
            acc[q] = fmaf(hv.w, w3, acc[q]);
        }
    }
#pragma unroll
    for (int q = 0; q < 8; q++)
        g_Wh[(size_t)(row0 + r0 + 4 * q) * FO + c] = acc[q];
}

// ============================================================
// K2: s1, s2 row dots
// ============================================================
__global__ __launch_bounds__(256) void k_s12(const float* __restrict__ a) {
    int i = blockIdx.x * 8 + (threadIdx.x >> 5);
    int l = threadIdx.x & 31;
    float wlo = g_Wh[(size_t)i * FO + l];
    float whi = g_Wh[(size_t)i * FO + 32 + l];
    float v1 = wlo * __ldg(&a[l]) + whi * __ldg(&a[32 + l]);
    float v2 = wlo * __ldg(&a[64 + l]) + whi * __ldg(&a[96 + l]);
#pragma unroll
    for (int o = 16; o; o >>= 1) {
        v1 += __shfl_xor_sync(0xffffffffu, v1, o);
        v2 += __shfl_xor_sync(0xffffffffu, v2, o);
    }
    if (l == 0) { g_s1[i] = v1; g_s2[i] = v2; }
}

// ============================================================
// K2b: Wh^T split to bf16 hi/lo pairs: g_WhT_*[c][jpair]
// ============================================================
__global__ __launch_bounds__(256) void k_prep() {
    int kp = blockIdx.x * 256 + threadIdx.x;   // 0..3071
    int c = blockIdx.y;                        // 0..63
    int j = kp * 2;
    float f0 = g_Wh[(size_t)j * FO + c];
    float f1 = g_Wh[(size_t)(j + 1) * FO + c];
    uint32_t hi = cvt_bf16x2(f0, f1);
    float h0 = __uint_as_float(hi << 16);
    float h1 = __uint_as_float(hi & 0xffff0000u);
    uint32_t lo = cvt_bf16x2(f0 - h0, f1 - h1);
    g_WhT_hi[c * (N / 2) + kp] = hi;
    g_WhT_lo[c * (N / 2) + kp] = lo;
}

// ============================================================
// K3: mask build + Z1 (one warp per row, single pass)
// ============================================================
__global__ __launch_bounds__(256) void k_stats(const int* __restrict__ adj,
                                               const float* __restrict__ aw) {
    int warp = threadIdx.x >> 5, lane = threadIdx.x & 31;
    int i = blockIdx.x * 8 + warp;

    float aw0 = __ldg(&aw[0]), aw1 = __ldg(&aw[1]);
    float ea = __expf(aw0), eb = __expf(aw1);
    float w0 = ea / (ea + eb);

    const int* row = adj + (size_t)i * N;
    float s1i = g_s1[i];
    float z = 0.f;

#pragma unroll 4
    for (int m = 0; m < N / 256; m++) {
        int jb = m * 256 + lane * 8;
        int4 v0 = __ldg((const int4*)(row + jb));
        int4 v1 = __ldg((const int4*)(row + jb + 4));
        float4 sa = *(const float4*)(g_s2 + jb);
        float4 sb = *(const float4*)(g_s2 + jb + 4);
        unsigned b = 0;
        float x;
        if (v0.x) { b |= 1u;   x = s1i + sa.x; z += __expf(fmaxf(x, ALPHA * x)); }
        if (v0.y) { b |= 2u;   x = s1i + sa.y; z += __expf(fmaxf(x, ALPHA * x)); }
        if (v0.z) { b |= 4u;   x = s1i + sa.z; z += __expf(fmaxf(x, ALPHA * x)); }
        if (v0.w) { b |= 8u;   x = s1i + sa.w; z += __expf(fmaxf(x, ALPHA * x)); }
        if (v1.x) { b |= 16u;  x = s1i + sb.x; z += __expf(fmaxf(x, ALPHA * x)); }
        if (v1.y) { b |= 32u;  x = s1i + sb.y; z += __expf(fmaxf(x, ALPHA * x)); }
        if (v1.z) { b |= 64u;  x = s1i + sb.z; z += __expf(fmaxf(x, ALPHA * x)); }
        if (v1.w) { b |= 128u; x = s1i + sb.w; z += __expf(fmaxf(x, ALPHA * x)); }
        g_mask8[(size_t)i * NB + m * 32 + lane] = (unsigned char)b;
    }
#pragma unroll
    for (int o = 16; o; o >>= 1) z += __shfl_xor_sync(0xffffffffu, z, o);
    if (lane == 0) g_al[i] = w0 / z;
}

// ============================================================
// K4: scores (SIMT/MUFU) -> bf16 hi/lo tiles -> HMMA PV (reg f32 accum)
// grid (48, 6) = 288 CTAs, 2/SM. Warp w owns rows [16w,16w+16).
// 3 MMA combos (hh, hl, lh) recover fp32-grade precision.
// ============================================================
__global__ __launch_bounds__(256, 2) void k_attn(const float* __restrict__ Mm,
                                                 const float* __restrict__ aw) {
    extern __shared__ char smem[];
    uint32_t sb = smem_u32(smem);
    int t = threadIdx.x, wid = t >> 5, lane = t & 31;
    int row0 = blockIdx.x * ROWS_T;
    int split = blockIdx.y;
    int j0 = split * JSP;

    float* s2s = (float*)(smem + SM_S2S);
    for (int k = t; k < JSP; k += 256) s2s[k] = g_s2[j0 + k];

    float aw0 = __ldg(&aw[0]), aw1 = __ldg(&aw[1]);
    float ea = __expf(aw0), eb = __expf(aw1);
    float w1 = eb / (ea + eb);

    // score mapping: 2 threads per row, 32 j each
    int rs = t >> 1, jq = t & 1;
    float s1r = g_s1[row0 + rs];
    float alr = g_al[row0 + rs];
    const float* Mrow = Mm + (size_t)(row0 + rs) * N + j0 + jq * 32;
    const unsigned char* mrowb = g_mask8 + (size_t)(row0 + rs) * NB + (j0 >> 3) + jq * 4;
    unsigned abyte = (unsigned)(rs * 128 + jq * 64);
    int jpb = j0 >> 1;

    // ldmatrix lane addressing
    int lr = lane & 7, sel = lane >> 3;
    int m0 = wid * 16;
    unsigned a_off = SWZ((unsigned)((m0 + lr + ((sel & 1) ? 8 : 0)) * 128));  // + k*2 later (k mult of 8 -> recompute)
    (void)a_off;

    float acc[8][4];
#pragma unroll
    for (int i = 0; i < 8; i++)
#pragma unroll
        for (int q = 0; q < 4; q++) acc[i][q] = 0.f;
    float zacc = 0.f;

    __syncthreads();

    for (int ch = 0; ch < NCHUNK; ch++) {
        // --- stage B chunk (WhT hi/lo), 2048 uints each ---
        {
            int jpB = jpb + ch * 32;
#pragma unroll
            for (int r = 0; r < 8; r++) {
                int id = t + 256 * r;
                int c = id >> 5, kp = id & 31;
                unsigned off = SWZ((unsigned)(c * 128 + kp * 4));
                *(unsigned*)(smem + SM_B_HI + off) = g_WhT_hi[c * (N / 2) + jpB + kp];
                *(unsigned*)(smem + SM_B_LO + off) = g_WhT_lo[c * (N / 2) + jpB + kp];
            }
        }
        // --- scores -> A hi/lo tiles (row-major [128][64] bf16, SW128) ---
        {
            int jb = ch * KCH;
            unsigned word = *(const unsigned*)(mrowb + (ch << 3));
#pragma unroll
            for (int k4 = 0; k4 < 8; k4++) {
                int kk = k4 * 4;
                float4 m4 = *(const float4*)(Mrow + jb + kk);
                float4 s4 = *(const float4*)(s2s + jb + jq * 32 + kk);
                float x, v, e1, tt, p0, p1, p2, p3;
                x = s1r + s4.x; v = fmaxf(x, ALPHA * x);
                e1 = alr * __expf(v); tt = fmaf(w1, m4.x, e1);
                p0 = ((word >> (kk + 0)) & 1u) ? __expf(tt) : 0.f;
                x = s1r + s4.y; v = fmaxf(x, ALPHA * x);
                e1 = alr * __expf(v); tt = fmaf(w1, m4.y, e1);
                p1 = ((word >> (kk + 1)) & 1u) ? __expf(tt) : 0.f;
                x = s1r + s4.z; v = fmaxf(x, ALPHA * x);
                e1 = alr * __expf(v); tt = fmaf(w1, m4.z, e1);
                p2 = ((word >> (kk + 2)) & 1u) ? __expf(tt) : 0.f;
                x = s1r + s4.w; v = fmaxf(x, ALPHA * x);
                e1 = alr * __expf(v); tt = fmaf(w1, m4.w, e1);
                p3 = ((word >> (kk + 3)) & 1u) ? __expf(tt) : 0.f;
                zacc += (p0 + p1) + (p2 + p3);

                uint32_t hA = cvt_bf16x2(p0, p1), hB = cvt_bf16x2(p2, p3);
                float r0 = p0 - __uint_as_float(hA << 16);
                float r1 = p1 - __uint_as_float(hA & 0xffff0000u);
                float r2 = p2 - __uint_as_float(hB << 16);
                float r3 = p3 - __uint_as_float(hB & 0xffff0000u);
                uint32_t lA = cvt_bf16x2(r0, r1), lB = cvt_bf16x2(r2, r3);
                unsigned off = SWZ(abyte + 2 * kk);
                *(uint2*)(smem + SM_A_HI + off) = make_uint2(hA, hB);
                *(uint2*)(smem + SM_A_LO + off) = make_uint2(lA, lB);
            }
        }
        __syncthreads();
        // --- HMMA: 4 k-steps x 8 n-tiles x 3 combos ---
#pragma unroll
        for (int ks = 0; ks < 4; ks++) {
            int kk = ks * 16;
            int arow = m0 + lr + ((sel & 1) ? 8 : 0);
            int acol = kk + ((sel & 2) ? 8 : 0);
            unsigned aoff = SWZ((unsigned)(arow * 128 + acol * 2));
            uint32_t ah[4], alr4[4];
            ldsm_x4(ah, sb + SM_A_HI + aoff);
            ldsm_x4(alr4, sb + SM_A_LO + aoff);
#pragma unroll
            for (int nt2 = 0; nt2 < 4; nt2++) {
                int n0 = nt2 * 16;
                int brow = n0 + lr + ((sel & 2) ? 8 : 0);
                int bcol = kk + ((sel & 1) ? 8 : 0);
                unsigned boff = SWZ((unsigned)(brow * 128 + bcol * 2));
                uint32_t bh[4], bl[4];
                ldsm_x4(bh, sb + SM_B_HI + boff);
                ldsm_x4(bl, sb + SM_B_LO + boff);
                mma_bf16(acc[nt2 * 2],     ah,   bh[0], bh[1]);
                mma_bf16(acc[nt2 * 2],     ah,   bl[0], bl[1]);
                mma_bf16(acc[nt2 * 2],     alr4, bh[0], bh[1]);
                mma_bf16(acc[nt2 * 2 + 1], ah,   bh[2], bh[3]);
                mma_bf16(acc[nt2 * 2 + 1], ah,   bl[2], bl[3]);
                mma_bf16(acc[nt2 * 2 + 1], alr4, bh[2], bh[3]);
            }
        }
        __syncthreads();
    }

    // Z2 partial (2 threads per row)
    zacc += __shfl_xor_sync(0xffffffffu, zacc, 1);
    if (jq == 0) g_Z2[split][row0 + rs] = zacc;

    // epilogue: fragment regs -> partial store
    {
        int g = lane >> 2, t4 = lane & 3;
        float* dst = &g_acc[split][0];
#pragma unroll
        for (int nt = 0; nt < 8; nt++) {
            int col = nt * 8 + 2 * t4;
            int ra = row0 + m0 + g;
            *(float2*)&dst[(size_t)ra * FO + col] = make_float2(acc[nt][0], acc[nt][1]);
            *(float2*)&dst[(size_t)(ra + 8) * FO + col] = make_float2(acc[nt][2], acc[nt][3]);
        }
    }
}

// ============================================================
// K5: combine splits, normalize, ELU
// ============================================================
__global__ __launch_bounds__(256) void k_out(float* __restrict__ out) {
    int idx = blockIdx.x * 256 + threadIdx.x;
    int i = idx >> 6;
    float z = 0.f, v = 0.f;
#pragma unroll
    for (int s = 0; s < SPLITS; s++) { z += g_Z2[s][i]; v += g_acc[s][idx]; }
    v /= z;
    out[idx] = v > 0.f ? v : (__expf(v) - 1.f);
}

// ============================================================
extern "C" void kernel_launch(void* const* d_in, const int* in_sizes, int n_in,
                              void* d_out, int out_size) {
    const float* h   = (const float*)d_in[0];
    const int*   adj = (const int*)d_in[1];
    const float* Mm  = (const float*)d_in[2];
    const float* W   = (const float*)d_in[3];
    const float* a   = (const float*)d_in[4];
    const float* aw  = (const float*)d_in[5];
    float* out = (float*)d_out;

    static int smem_set = 0;
    if (!smem_set) {
        cudaFuncSetAttribute(k_attn, cudaFuncAttributeMaxDynamicSharedMemorySize, SM_TOTAL);
        smem_set = 1;
    }

    k_wh   <<<N / 32, 256>>>(h, W);
    k_s12  <<<N / 8, 256>>>(a);
    k_prep <<<dim3(N / 2 / 256, FO), 256>>>();
    k_stats<<<N / 8, 256>>>(adj, aw);
    k_attn <<<dim3(N / ROWS_T, SPLITS), 256, SM_TOTAL>>>(Mm, aw);
    k_out  <<<N * FO / 256, 256>>>(out);
}